// round 2
// baseline (speedup 1.0000x reference)
#include <cuda_runtime.h>
#include <cstdint>

// ---------------------------------------------------------------------------
// Problem constants
// ---------------------------------------------------------------------------
#define M_MODES 10
#define N_PHOT  5
#define N_NB    252     // C(10,5)
#define N_B     2002    // C(14,5)
#define MAX_B   256
#define S2      8       // stage-2 blocks per batch element
#define T2      128     // stage-2 threads per block

// __device__ global scratch (no allocations allowed)
__device__ float2 g_WR1[10][10];
__device__ float2 g_WL1c[10][5];   // WL1[:, IN_MODES]
__device__ float2 g_WRF[10][10];
__device__ float2 g_WLFc[10][5];   // WLF[:, IN_MODES]
__device__ unsigned g_rows_nb[N_NB];      // 5 modes packed 4 bits each
__device__ unsigned g_rows_b[N_B];
__device__ float    g_inv_norm_b[N_B];
__device__ float2   g_VF[MAX_B][10][5];          // per-batch final effective unitary
__device__ float    g_partial[MAX_B][S2][10];    // per-chunk output partials

// ---------------------------------------------------------------------------
// complex helpers
// ---------------------------------------------------------------------------
__device__ __forceinline__ float2 cmul(float2 a, float2 b) {
    return make_float2(fmaf(a.x, b.x, -a.y * b.y), fmaf(a.x, b.y, a.y * b.x));
}
__device__ __forceinline__ float2 cadd(float2 a, float2 b) {
    return make_float2(a.x + b.x, a.y + b.y);
}

__device__ __forceinline__ long binom(int n, int k) {
    if (k < 0 || n < 0 || k > n) return 0;
    long r = 1;
    for (int i = 1; i <= k; i++) r = r * (n - k + i) / i;
    return r;
}

// ---------------------------------------------------------------------------
// Setup kernel: interferometers + Fock row tables
// ---------------------------------------------------------------------------
__global__ void setup_kernel(const float* __restrict__ ph_l1,
                             const float* __restrict__ ph_r1,
                             const float* __restrict__ ph_lf,
                             const float* __restrict__ ph_rf) {
    if (blockIdx.x == 0) {
        __shared__ float2 T[4][45][4];
        int t = threadIdx.x;
        if (t < 180) {
            int g = t / 45, k = t % 45;
            const float* ph = (g == 0) ? ph_l1 : (g == 1) ? ph_r1 : (g == 2) ? ph_lf : ph_rf;
            float t1 = ph[2 * k], t2 = ph[2 * k + 1];
            float s1, c1, s2, c2v;
            sincosf(t1, &s1, &c1);
            sincosf(t2, &s2, &c2v);
            float2 e1 = make_float2(c1, s1), e2 = make_float2(c2v, s2);
            const float s = 0.7071067811865476f;
            float2 B00 = make_float2(s, 0), B01 = make_float2(0, s);
            float2 B10 = make_float2(0, s), B11 = make_float2(s, 0);
            float2 M100 = cmul(e1, B00), M101 = cmul(e1, B01);
            float2 M110 = B10, M111 = B11;
            float2 M200 = cadd(cmul(B00, M100), cmul(B01, M110));
            float2 M201 = cadd(cmul(B00, M101), cmul(B01, M111));
            float2 M210 = cadd(cmul(B10, M100), cmul(B11, M110));
            float2 M211 = cadd(cmul(B10, M101), cmul(B11, M111));
            T[g][k][0] = cmul(e2, M200);
            T[g][k][1] = cmul(e2, M201);
            T[g][k][2] = M210;
            T[g][k][3] = M211;
        }
        __syncthreads();
        if (t < 40) {
            int g = t / 10, col = t % 10;
            float2 u[10];
            #pragma unroll
            for (int m = 0; m < 10; m++) u[m] = make_float2(m == col ? 1.f : 0.f, 0.f);
            int k = 0;
            for (int layer = 0; layer < 10; layer++) {
                for (int p = (layer & 1); p < 9; p += 2) {
                    float2 a = u[p], b = u[p + 1];
                    u[p]     = cadd(cmul(T[g][k][0], a), cmul(T[g][k][1], b));
                    u[p + 1] = cadd(cmul(T[g][k][2], a), cmul(T[g][k][3], b));
                    k++;
                }
            }
            if (g == 0) {
                if ((col & 1) == 0)
                    for (int m = 0; m < 10; m++) g_WL1c[m][col >> 1] = u[m];
            } else if (g == 1) {
                for (int m = 0; m < 10; m++) g_WR1[m][col] = u[m];
            } else if (g == 2) {
                if ((col & 1) == 0)
                    for (int m = 0; m < 10; m++) g_WLFc[m][col >> 1] = u[m];
            } else {
                for (int m = 0; m < 10; m++) g_WRF[m][col] = u[m];
            }
        }
    } else {
        int idx = (blockIdx.x - 1) * blockDim.x + threadIdx.x;
        if (idx < N_NB) {
            int r = idx, x = 0;
            unsigned packed = 0;
            for (int pos = 0; pos < 5; pos++) {
                for (;;) {
                    long cnt = binom(9 - x, 4 - pos);
                    if (r < cnt) break;
                    r -= (int)cnt;
                    x++;
                }
                packed |= (unsigned)x << (4 * pos);
                x++;
            }
            g_rows_nb[idx] = packed;
        } else if (idx < N_NB + N_B) {
            int rank = idx - N_NB;
            int r = rank, x = 0;
            int row[5];
            for (int pos = 0; pos < 5; pos++) {
                for (;;) {
                    long cnt = binom(13 - x, 4 - pos);
                    if (r < cnt) break;
                    r -= (int)cnt;
                    x++;
                }
                row[pos] = x - pos;
                x++;
            }
            unsigned packed = 0;
            int cnt_[10];
            #pragma unroll
            for (int m = 0; m < 10; m++) cnt_[m] = 0;
            #pragma unroll
            for (int pos = 0; pos < 5; pos++) {
                packed |= (unsigned)row[pos] << (4 * pos);
                cnt_[row[pos]]++;
            }
            const float fact[6] = {1.f, 1.f, 2.f, 6.f, 24.f, 120.f};
            float norm = 1.f;
            #pragma unroll
            for (int m = 0; m < 10; m++) norm *= fact[cnt_[m]];
            g_rows_b[rank] = packed;
            g_inv_norm_b[rank] = 1.0f / norm;
        }
    }
}

// ---------------------------------------------------------------------------
// Glynn permanent |perm|^2, Gray-code over 16 sign vectors.
// Product chain restructured as a tree: ((r0*r1)*(r2*r3))*r4.
// ---------------------------------------------------------------------------
__device__ __forceinline__ float perm_prob(const float2 (*__restrict__ V)[5], unsigned packed) {
    float2 M[5][5];
    #pragma unroll
    for (int i = 0; i < 5; i++) {
        int ri = (packed >> (4 * i)) & 15;
        #pragma unroll
        for (int j = 0; j < 5; j++) M[i][j] = V[ri][j];
    }
    float2 rs[5];
    #pragma unroll
    for (int j = 0; j < 5; j++) {
        rs[j].x = M[0][j].x + M[1][j].x + M[2][j].x + M[3][j].x + M[4][j].x;
        rs[j].y = M[0][j].y + M[1][j].y + M[2][j].y + M[3][j].y + M[4][j].y;
    }
    float sx = 0.f, sy = 0.f;
    #pragma unroll
    for (int g = 0; g < 16; g++) {
        float2 p01 = cmul(rs[0], rs[1]);
        float2 p23 = cmul(rs[2], rs[3]);
        float2 p = cmul(cmul(p01, p23), rs[4]);
        if (g & 1) { sx -= p.x; sy -= p.y; }
        else       { sx += p.x; sy += p.y; }
        if (g < 15) {
            int gc = g ^ (g >> 1);
            int gn = (g + 1) ^ ((g + 1) >> 1);
            int diff = gc ^ gn;
            int bit = __ffs(diff) - 1;
            int i = bit + 1;
            float dlt = (gn & diff) ? -2.f : 2.f;
            #pragma unroll
            for (int j = 0; j < 5; j++) {
                rs[j].x = fmaf(dlt, M[i][j].x, rs[j].x);
                rs[j].y = fmaf(dlt, M[i][j].y, rs[j].y);
            }
        }
    }
    sx *= 0.0625f;
    sy *= 0.0625f;
    return fmaf(sx, sx, sy * sy);
}

// ---------------------------------------------------------------------------
// Stage 1: per batch element -> VF (proj, U1 build, 252 perms, phi2, VF build)
// 128 blocks x 256 threads
// ---------------------------------------------------------------------------
__global__ __launch_bounds__(256)
void stage1(const float* __restrict__ x, const float* __restrict__ Wd,
            const float* __restrict__ bd) {
    int b = blockIdx.x;
    int t = threadIdx.x;
    int lane = t & 31;
    int w = t >> 5;  // 8 warps

    __shared__ float2 sh_eih[10];
    __shared__ float2 sh_V[10][5];
    __shared__ float  sh_e1[N_NB];

    // 1. h = (x@Wd + bd)/pi : warp w handles modes w, w+8
    for (int mode = w; mode < 10; mode += 8) {
        float acc = 0.f;
        const float* xb = x + b * 784;
        for (int i = lane; i < 784; i += 32) acc = fmaf(xb[i], Wd[i * 10 + mode], acc);
        #pragma unroll
        for (int o = 16; o; o >>= 1) acc += __shfl_xor_sync(0xffffffffu, acc, o);
        if (lane == 0) {
            float h = (acc + bd[mode]) * 0.3183098861837907f;  // 1/pi
            float s, c;
            sincosf(h, &s, &c);
            sh_eih[mode] = make_float2(c, s);
        }
    }
    __syncthreads();

    // 2. V1[m][j] = sum_k WR1[m][k] * e^{ih_k} * WL1c[k][j]
    if (t < 50) {
        int m = t / 5, j = t % 5;
        float2 s = make_float2(0.f, 0.f);
        #pragma unroll
        for (int k = 0; k < 10; k++)
            s = cadd(s, cmul(g_WR1[m][k], cmul(sh_eih[k], g_WL1c[k][j])));
        sh_V[m][j] = s;
    }
    __syncthreads();

    // 3. 252 no-bunching probabilities (norm = 1)
    if (t < N_NB) sh_e1[t] = perm_prob(sh_V, g_rows_nb[t]);
    __syncthreads();

    // 4. phi2[m] = sum_j e1[m + 10j]; then e^{i phi2}
    if (t < 10) {
        float phi = 0.f;
        for (int j2 = t; j2 < N_NB; j2 += 10) phi += sh_e1[j2];
        float s, c;
        sincosf(phi, &s, &c);
        sh_eih[t] = make_float2(c, s);
    }
    __syncthreads();

    // 5. VF[m][j] -> global
    if (t < 50) {
        int m = t / 5, j = t % 5;
        float2 s = make_float2(0.f, 0.f);
        #pragma unroll
        for (int k = 0; k < 10; k++)
            s = cadd(s, cmul(g_WRF[m][k], cmul(sh_eih[k], g_WLFc[k][j])));
        g_VF[b][m][j] = s;
    }
}

// ---------------------------------------------------------------------------
// Stage 2: bunched permanents fused with probs @ W_out, split S2-ways.
// grid = B * S2 blocks x T2 threads. Block (b,s) handles k ≡ s (mod S2).
// ---------------------------------------------------------------------------
__global__ __launch_bounds__(T2)
void stage2(const float* __restrict__ Wo) {
    int bid = blockIdx.x;
    int b = bid >> 3;        // / S2
    int s = bid & (S2 - 1);
    int t = threadIdx.x;
    int lane = t & 31;
    int w = t >> 5;          // 4 warps

    __shared__ float2 sh_V[10][5];
    __shared__ float  sh_red[T2 / 32][10];

    if (t < 50) {
        int m = t / 5, j = t % 5;
        sh_V[m][j] = g_VF[b][m][j];
    }
    __syncthreads();

    float acc[10];
    #pragma unroll
    for (int c = 0; c < 10; c++) acc[c] = 0.f;

    #pragma unroll
    for (int i = 0; i < 2; i++) {
        int k = s + S2 * (t + T2 * i);
        if (k < N_B) {
            float p = perm_prob(sh_V, g_rows_b[k]) * g_inv_norm_b[k];
            const float* wr = Wo + k * 10;
            #pragma unroll
            for (int c = 0; c < 10; c++) acc[c] = fmaf(p, wr[c], acc[c]);
        }
    }

    #pragma unroll
    for (int c = 0; c < 10; c++) {
        #pragma unroll
        for (int o = 16; o; o >>= 1) acc[c] += __shfl_xor_sync(0xffffffffu, acc[c], o);
    }
    if (lane == 0) {
        #pragma unroll
        for (int c = 0; c < 10; c++) sh_red[w][c] = acc[c];
    }
    __syncthreads();
    if (t < 10) {
        float v = 0.f;
        #pragma unroll
        for (int ww = 0; ww < T2 / 32; ww++) v += sh_red[ww][t];
        g_partial[b][s][t] = v;
    }
}

// ---------------------------------------------------------------------------
// Stage 3: deterministic fixed-order reduction of the S2 partials + bias.
// ---------------------------------------------------------------------------
__global__ void stage3(const float* __restrict__ bo, float* __restrict__ out, int B) {
    int idx = blockIdx.x * blockDim.x + threadIdx.x;
    if (idx < B * 10) {
        int b = idx / 10, c = idx % 10;
        float v = bo[c];
        #pragma unroll
        for (int s = 0; s < S2; s++) v += g_partial[b][s][c];
        out[idx] = v;
    }
}

// ---------------------------------------------------------------------------
extern "C" void kernel_launch(void* const* d_in, const int* in_sizes, int n_in,
                              void* d_out, int out_size) {
    const float* x   = (const float*)d_in[0];
    const float* Wd  = (const float*)d_in[1];
    const float* bd  = (const float*)d_in[2];
    const float* pl1 = (const float*)d_in[3];
    const float* pr1 = (const float*)d_in[4];
    const float* plf = (const float*)d_in[5];
    const float* prf = (const float*)d_in[6];
    const float* Wo  = (const float*)d_in[7];
    const float* bo  = (const float*)d_in[8];
    float* out = (float*)d_out;

    int B = in_sizes[0] / 784;

    setup_kernel<<<10, 256>>>(pl1, pr1, plf, prf);
    stage1<<<B, 256>>>(x, Wd, bd);
    stage2<<<B * S2, T2>>>(Wo);
    stage3<<<(B * 10 + 255) / 256, 256>>>(bo, out, B);
}

// round 3
// speedup vs baseline: 1.3018x; 1.3018x over previous
#include <cuda_runtime.h>
#include <cstdint>

// ---------------------------------------------------------------------------
#define M_MODES 10
#define N_PHOT  5
#define N_NB    252     // C(10,5)
#define N_B     2002    // C(14,5)

// __device__ global tables (no allocations allowed)
__device__ float2 g_WR1[10][10];
__device__ float2 g_WL1c[10][5];   // WL1[:, IN_MODES]
__device__ float2 g_WRF[10][10];
__device__ float2 g_WLFc[10][5];   // WLF[:, IN_MODES]
__device__ unsigned g_rows_nb[N_NB];   // 5 modes packed 4 bits each
__device__ unsigned g_rows_b[N_B];
__device__ float    g_inv_norm_b[N_B];

// ---------------------------------------------------------------------------
__device__ __forceinline__ float2 cmul(float2 a, float2 b) {
    return make_float2(fmaf(a.x, b.x, -a.y * b.y), fmaf(a.x, b.y, a.y * b.x));
}
__device__ __forceinline__ float2 cadd(float2 a, float2 b) {
    return make_float2(a.x + b.x, a.y + b.y);
}

__device__ __forceinline__ long binom(int n, int k) {
    if (k < 0 || n < 0 || k > n) return 0;
    long r = 1;
    for (int i = 1; i <= k; i++) r = r * (n - k + i) / i;
    return r;
}

// ---------------------------------------------------------------------------
// Setup: interferometers + Fock tables + zero-init of out (runs before main
// in stream order -> graph dependency).
// grid: 10 + ceil(B*10/256) blocks x 256 threads.
// ---------------------------------------------------------------------------
__global__ void setup_kernel(const float* __restrict__ ph_l1,
                             const float* __restrict__ ph_r1,
                             const float* __restrict__ ph_lf,
                             const float* __restrict__ ph_rf,
                             float* __restrict__ out, int Bten) {
    if (blockIdx.x >= 10) {
        int i = (blockIdx.x - 10) * 256 + threadIdx.x;
        if (i < Bten) out[i] = 0.f;
        return;
    }
    if (blockIdx.x == 0) {
        __shared__ float2 T[4][45][4];
        int t = threadIdx.x;
        if (t < 180) {
            int g = t / 45, k = t % 45;
            const float* ph = (g == 0) ? ph_l1 : (g == 1) ? ph_r1 : (g == 2) ? ph_lf : ph_rf;
            float t1 = ph[2 * k], t2 = ph[2 * k + 1];
            float s1, c1, s2, c2v;
            sincosf(t1, &s1, &c1);
            sincosf(t2, &s2, &c2v);
            float2 e1 = make_float2(c1, s1), e2 = make_float2(c2v, s2);
            const float s = 0.7071067811865476f;
            float2 B00 = make_float2(s, 0), B01 = make_float2(0, s);
            float2 B10 = make_float2(0, s), B11 = make_float2(s, 0);
            float2 M100 = cmul(e1, B00), M101 = cmul(e1, B01);
            float2 M110 = B10, M111 = B11;
            float2 M200 = cadd(cmul(B00, M100), cmul(B01, M110));
            float2 M201 = cadd(cmul(B00, M101), cmul(B01, M111));
            float2 M210 = cadd(cmul(B10, M100), cmul(B11, M110));
            float2 M211 = cadd(cmul(B10, M101), cmul(B11, M111));
            T[g][k][0] = cmul(e2, M200);
            T[g][k][1] = cmul(e2, M201);
            T[g][k][2] = M210;
            T[g][k][3] = M211;
        }
        __syncthreads();
        if (t < 40) {
            int g = t / 10, col = t % 10;
            float2 u[10];
            #pragma unroll
            for (int m = 0; m < 10; m++) u[m] = make_float2(m == col ? 1.f : 0.f, 0.f);
            int k = 0;
            for (int layer = 0; layer < 10; layer++) {
                for (int p = (layer & 1); p < 9; p += 2) {
                    float2 a = u[p], b = u[p + 1];
                    u[p]     = cadd(cmul(T[g][k][0], a), cmul(T[g][k][1], b));
                    u[p + 1] = cadd(cmul(T[g][k][2], a), cmul(T[g][k][3], b));
                    k++;
                }
            }
            if (g == 0) {
                if ((col & 1) == 0)
                    for (int m = 0; m < 10; m++) g_WL1c[m][col >> 1] = u[m];
            } else if (g == 1) {
                for (int m = 0; m < 10; m++) g_WR1[m][col] = u[m];
            } else if (g == 2) {
                if ((col & 1) == 0)
                    for (int m = 0; m < 10; m++) g_WLFc[m][col >> 1] = u[m];
            } else {
                for (int m = 0; m < 10; m++) g_WRF[m][col] = u[m];
            }
        }
    } else {
        int idx = (blockIdx.x - 1) * blockDim.x + threadIdx.x;
        if (idx < N_NB) {
            int r = idx, x = 0;
            unsigned packed = 0;
            for (int pos = 0; pos < 5; pos++) {
                for (;;) {
                    long cnt = binom(9 - x, 4 - pos);
                    if (r < cnt) break;
                    r -= (int)cnt;
                    x++;
                }
                packed |= (unsigned)x << (4 * pos);
                x++;
            }
            g_rows_nb[idx] = packed;
        } else if (idx < N_NB + N_B) {
            int rank = idx - N_NB;
            int r = rank, x = 0;
            int row[5];
            for (int pos = 0; pos < 5; pos++) {
                for (;;) {
                    long cnt = binom(13 - x, 4 - pos);
                    if (r < cnt) break;
                    r -= (int)cnt;
                    x++;
                }
                row[pos] = x - pos;
                x++;
            }
            unsigned packed = 0;
            int cnt_[10];
            #pragma unroll
            for (int m = 0; m < 10; m++) cnt_[m] = 0;
            #pragma unroll
            for (int pos = 0; pos < 5; pos++) {
                packed |= (unsigned)row[pos] << (4 * pos);
                cnt_[row[pos]]++;
            }
            const float fact[6] = {1.f, 1.f, 2.f, 6.f, 24.f, 120.f};
            float norm = 1.f;
            #pragma unroll
            for (int m = 0; m < 10; m++) norm *= fact[cnt_[m]];
            g_rows_b[rank] = packed;
            g_inv_norm_b[rank] = 1.0f / norm;
        }
    }
}

// ---------------------------------------------------------------------------
// Glynn |perm|^2, Gray-code over 16 sign vectors, product as 3-deep tree.
// ---------------------------------------------------------------------------
__device__ __forceinline__ float perm_prob(const float2 (*__restrict__ V)[5], unsigned packed) {
    float2 M[5][5];
    #pragma unroll
    for (int i = 0; i < 5; i++) {
        int ri = (packed >> (4 * i)) & 15;
        #pragma unroll
        for (int j = 0; j < 5; j++) M[i][j] = V[ri][j];
    }
    float2 rs[5];
    #pragma unroll
    for (int j = 0; j < 5; j++) {
        rs[j].x = M[0][j].x + M[1][j].x + M[2][j].x + M[3][j].x + M[4][j].x;
        rs[j].y = M[0][j].y + M[1][j].y + M[2][j].y + M[3][j].y + M[4][j].y;
    }
    float sx = 0.f, sy = 0.f;
    #pragma unroll
    for (int g = 0; g < 16; g++) {
        float2 p01 = cmul(rs[0], rs[1]);
        float2 p23 = cmul(rs[2], rs[3]);
        float2 p = cmul(cmul(p01, p23), rs[4]);
        if (g & 1) { sx -= p.x; sy -= p.y; }
        else       { sx += p.x; sy += p.y; }
        if (g < 15) {
            int gc = g ^ (g >> 1);
            int gn = (g + 1) ^ ((g + 1) >> 1);
            int diff = gc ^ gn;
            int bit = __ffs(diff) - 1;
            int i = bit + 1;
            float dlt = (gn & diff) ? -2.f : 2.f;
            #pragma unroll
            for (int j = 0; j < 5; j++) {
                rs[j].x = fmaf(dlt, M[i][j].x, rs[j].x);
                rs[j].y = fmaf(dlt, M[i][j].y, rs[j].y);
            }
        }
    }
    sx *= 0.0625f;
    sy *= 0.0625f;
    return fmaf(sx, sx, sy * sy);
}

// ---------------------------------------------------------------------------
// Fused main: 2 blocks per batch element. Both compute stage 1; each does
// half the 2002 bunched permanents; combine via exactly-2 atomicAdds per
// output (bitwise deterministic: two-term fp add is commutative).
// ---------------------------------------------------------------------------
__global__ __launch_bounds__(256, 3)
void qc_main(const float* __restrict__ x, const float* __restrict__ Wd,
             const float* __restrict__ bd, const float* __restrict__ Wo,
             const float* __restrict__ bo, float* __restrict__ out) {
    int bid = blockIdx.x;
    int b = bid >> 1;
    int s = bid & 1;
    int t = threadIdx.x;
    int lane = t & 31;
    int w = t >> 5;  // 8 warps

    __shared__ float2 sh_eih[10];
    __shared__ float2 sh_V[10][5];
    __shared__ float  sh_e1[N_NB];
    __shared__ float  sh_red[8][10];

    // 1. h = (x@Wd + bd)/pi : warp w handles modes w (and w+8 for w<2)
    for (int mode = w; mode < 10; mode += 8) {
        float acc = 0.f;
        const float* xb = x + b * 784;
        for (int i = lane; i < 784; i += 32) acc = fmaf(xb[i], Wd[i * 10 + mode], acc);
        #pragma unroll
        for (int o = 16; o; o >>= 1) acc += __shfl_xor_sync(0xffffffffu, acc, o);
        if (lane == 0) {
            float h = (acc + bd[mode]) * 0.3183098861837907f;  // 1/pi
            float sn, cs;
            sincosf(h, &sn, &cs);
            sh_eih[mode] = make_float2(cs, sn);
        }
    }
    __syncthreads();

    // 2. V1[m][j] = sum_k WR1[m][k] * e^{ih_k} * WL1c[k][j]
    if (t < 50) {
        int m = t / 5, j = t % 5;
        float2 v = make_float2(0.f, 0.f);
        #pragma unroll
        for (int k = 0; k < 10; k++)
            v = cadd(v, cmul(g_WR1[m][k], cmul(sh_eih[k], g_WL1c[k][j])));
        sh_V[m][j] = v;
    }
    __syncthreads();

    // 3. 252 no-bunching probabilities (norm = 1)
    if (t < N_NB) sh_e1[t] = perm_prob(sh_V, g_rows_nb[t]);
    __syncthreads();

    // 4. phi2[m] = sum_j e1[m + 10j]; then e^{i phi2}
    if (t < 10) {
        float phi = 0.f;
        for (int j2 = t; j2 < N_NB; j2 += 10) phi += sh_e1[j2];
        float sn, cs;
        sincosf(phi, &sn, &cs);
        sh_eih[t] = make_float2(cs, sn);
    }
    __syncthreads();

    // 5. VF[m][j]
    if (t < 50) {
        int m = t / 5, j = t % 5;
        float2 v = make_float2(0.f, 0.f);
        #pragma unroll
        for (int k = 0; k < 10; k++)
            v = cadd(v, cmul(g_WRF[m][k], cmul(sh_eih[k], g_WLFc[k][j])));
        sh_V[m][j] = v;
    }
    __syncthreads();

    // 6. this block's half of the 2002 bunched perms, fused with probs @ W_out
    float acc[10];
    #pragma unroll
    for (int c = 0; c < 10; c++) acc[c] = 0.f;
    #pragma unroll
    for (int iter = 0; iter < 4; iter++) {
        int k = s + 2 * (iter * 256 + t);
        if (k < N_B) {
            float p = perm_prob(sh_V, g_rows_b[k]) * g_inv_norm_b[k];
            const float* wr = Wo + k * 10;
            #pragma unroll
            for (int c = 0; c < 10; c++) acc[c] = fmaf(p, wr[c], acc[c]);
        }
    }

    #pragma unroll
    for (int c = 0; c < 10; c++) {
        #pragma unroll
        for (int o = 16; o; o >>= 1) acc[c] += __shfl_xor_sync(0xffffffffu, acc[c], o);
    }
    if (lane == 0) {
        #pragma unroll
        for (int c = 0; c < 10; c++) sh_red[w][c] = acc[c];
    }
    __syncthreads();
    if (t < 10) {
        float v = (s == 0) ? bo[t] : 0.f;
        #pragma unroll
        for (int ww = 0; ww < 8; ww++) v += sh_red[ww][t];
        atomicAdd(&out[b * 10 + t], v);   // exactly 2 adds per address -> deterministic
    }
}

// ---------------------------------------------------------------------------
extern "C" void kernel_launch(void* const* d_in, const int* in_sizes, int n_in,
                              void* d_out, int out_size) {
    const float* x   = (const float*)d_in[0];
    const float* Wd  = (const float*)d_in[1];
    const float* bd  = (const float*)d_in[2];
    const float* pl1 = (const float*)d_in[3];
    const float* pr1 = (const float*)d_in[4];
    const float* plf = (const float*)d_in[5];
    const float* prf = (const float*)d_in[6];
    const float* Wo  = (const float*)d_in[7];
    const float* bo  = (const float*)d_in[8];
    float* out = (float*)d_out;

    int B = in_sizes[0] / 784;
    int initBlocks = (B * 10 + 255) / 256;

    setup_kernel<<<10 + initBlocks, 256>>>(pl1, pr1, plf, prf, out, B * 10);
    qc_main<<<2 * B, 256>>>(x, Wd, bd, Wo, bo, out);
}